// round 4
// baseline (speedup 1.0000x reference)
#include <cuda_runtime.h>
#include <cuda_bf16.h>
#include <cstdint>

#define NN 50000
#define EE 800000
#define LN_EPS 1e-5f
#define ST 36

// ===================== static scratch =====================
__device__ int   g_deg[NN];
__device__ int   g_rowptr[NN + 1];
__device__ int   g_cursor[NN];
__device__ int   g_csrsrc[EE];
__device__ float g_invdeg[NN];
__device__ float g_agg0[(size_t)NN * 64];
__device__ float g_h0[2][(size_t)NN * 128];
__device__ float g_agg1[2][(size_t)NN * 128];
__device__ float g_h1[2][(size_t)NN * 128];
__device__ float g_P[2][(size_t)NN * 64];

struct TowerArgs {
    const float *Agg, *Hin, *Wl, *Wr, *bl, *gam, *bet;
    float *out, *out2;
};

__device__ __forceinline__ float to_tf32(float x) {
    uint32_t u;
    asm("cvt.rna.tf32.f32 %0, %1;" : "=r"(u) : "f"(x));
    return __uint_as_float(u);
}

__device__ __forceinline__ void mma_tf32(float& d0, float& d1, float& d2, float& d3,
                                         uint32_t a0, uint32_t a1, uint32_t a2, uint32_t a3,
                                         uint32_t b0, uint32_t b1) {
    asm volatile(
        "mma.sync.aligned.m16n8k8.row.col.f32.tf32.tf32.f32 "
        "{%0,%1,%2,%3}, {%4,%5,%6,%7}, {%8,%9}, {%0,%1,%2,%3};"
        : "+f"(d0), "+f"(d1), "+f"(d2), "+f"(d3)
        : "r"(a0), "r"(a1), "r"(a2), "r"(a3), "r"(b0), "r"(b1));
}

// ===================== CSR build =====================
__global__ void k_count(const int* __restrict__ dst, int* __restrict__ deg) {
    int e = blockIdx.x * blockDim.x + threadIdx.x;
    if (e < EE) atomicAdd(&deg[dst[e]], 1);
}

__global__ void k_scan(const int* __restrict__ deg, int* __restrict__ rowptr,
                       int* __restrict__ cursor) {
    __shared__ int sums[1024];
    const int t = threadIdx.x;
    const int CH = (NN + 1023) / 1024;
    int s = 0;
    #pragma unroll 4
    for (int i = 0; i < CH; ++i) {
        int idx = t * CH + i;
        if (idx < NN) s += deg[idx];
    }
    sums[t] = s;
    __syncthreads();
    for (int off = 1; off < 1024; off <<= 1) {
        int v = 0;
        if (t >= off) v = sums[t - off];
        __syncthreads();
        if (t >= off) sums[t] += v;
        __syncthreads();
    }
    int run = (t == 0) ? 0 : sums[t - 1];
    for (int i = 0; i < CH; ++i) {
        int idx = t * CH + i;
        if (idx < NN) {
            rowptr[idx] = run;
            cursor[idx] = run;
            run += deg[idx];
        }
    }
    if (t == 1023) rowptr[NN] = run;
}

__global__ void k_invdeg(const int* __restrict__ deg, float* __restrict__ invdeg) {
    int n = blockIdx.x * blockDim.x + threadIdx.x;
    if (n < NN) {
        int d = deg[n];
        invdeg[n] = 1.0f / (float)(d > 0 ? d : 1);
    }
}

__global__ void k_scatter(const int* __restrict__ src, const int* __restrict__ dst,
                          int* __restrict__ cursor, int* __restrict__ csrsrc) {
    int e = blockIdx.x * blockDim.x + threadIdx.x;
    if (e < EE) {
        int pos = atomicAdd(&cursor[dst[e]], 1);
        csrsrc[pos] = src[e];
    }
}

// ===================== gathers =====================
// mean-gather of 64-wide rows (single tower; used for agg0)
__global__ void k_gather64(const float* __restrict__ h, float* __restrict__ out,
                           const int* __restrict__ rowptr, const int* __restrict__ csrsrc,
                           const float* __restrict__ invdeg) {
    int gw   = (blockIdx.x * blockDim.x + threadIdx.x) >> 5;
    int lane = threadIdx.x & 31;
    if (gw >= NN) return;
    int s = rowptr[gw], e = rowptr[gw + 1];
    float2 a0 = make_float2(0, 0), a1 = make_float2(0, 0);
    int j = s;
    for (; j + 1 < e; j += 2) {
        int s0 = csrsrc[j], s1 = csrsrc[j + 1];
        float2 v0 = *(const float2*)(h + (size_t)s0 * 64 + lane * 2);
        float2 v1 = *(const float2*)(h + (size_t)s1 * 64 + lane * 2);
        a0.x += v0.x; a0.y += v0.y;
        a1.x += v1.x; a1.y += v1.y;
    }
    if (j < e) {
        int s0 = csrsrc[j];
        float2 v0 = *(const float2*)(h + (size_t)s0 * 64 + lane * 2);
        a0.x += v0.x; a0.y += v0.y;
    }
    float iv = invdeg[gw];
    float2 r;
    r.x = (a0.x + a1.x) * iv; r.y = (a0.y + a1.y) * iv;
    *(float2*)(out + (size_t)gw * 64 + lane * 2) = r;
}

// mean-gather of 128-wide rows, dual tower via blockIdx.y
__global__ void k_gather128_2(const float* __restrict__ hA, float* __restrict__ oA,
                              const float* __restrict__ hB, float* __restrict__ oB,
                              const int* __restrict__ rowptr, const int* __restrict__ csrsrc,
                              const float* __restrict__ invdeg) {
    const float* __restrict__ h = blockIdx.y ? hB : hA;
    float* __restrict__ out     = blockIdx.y ? oB : oA;
    int gw   = (blockIdx.x * blockDim.x + threadIdx.x) >> 5;
    int lane = threadIdx.x & 31;
    if (gw >= NN) return;
    int s = rowptr[gw], e = rowptr[gw + 1];
    float4 a0 = make_float4(0, 0, 0, 0), a1 = make_float4(0, 0, 0, 0);
    int j = s;
    for (; j + 1 < e; j += 2) {
        int s0 = csrsrc[j], s1 = csrsrc[j + 1];
        float4 v0 = *(const float4*)(h + (size_t)s0 * 128 + lane * 4);
        float4 v1 = *(const float4*)(h + (size_t)s1 * 128 + lane * 4);
        a0.x += v0.x; a0.y += v0.y; a0.z += v0.z; a0.w += v0.w;
        a1.x += v1.x; a1.y += v1.y; a1.z += v1.z; a1.w += v1.w;
    }
    if (j < e) {
        int s0 = csrsrc[j];
        float4 v0 = *(const float4*)(h + (size_t)s0 * 128 + lane * 4);
        a0.x += v0.x; a0.y += v0.y; a0.z += v0.z; a0.w += v0.w;
    }
    float iv = invdeg[gw];
    float4 r;
    r.x = (a0.x + a1.x) * iv; r.y = (a0.y + a1.y) * iv;
    r.z = (a0.z + a1.z) * iv; r.w = (a0.w + a1.w) * iv;
    *(float4*)(out + (size_t)gw * 128 + lane * 4) = r;
}

// mean-gather of 64-wide P, ADD into out (layer-2 commuted aggregation), dual tower
__global__ void k_gadd64_2(const float* __restrict__ PA, float* __restrict__ oA,
                           const float* __restrict__ PB, float* __restrict__ oB,
                           const int* __restrict__ rowptr, const int* __restrict__ csrsrc,
                           const float* __restrict__ invdeg) {
    const float* __restrict__ P = blockIdx.y ? PB : PA;
    float* __restrict__ out     = blockIdx.y ? oB : oA;
    int gw   = (blockIdx.x * blockDim.x + threadIdx.x) >> 5;
    int lane = threadIdx.x & 31;
    if (gw >= NN) return;
    int s = rowptr[gw], e = rowptr[gw + 1];
    float2 a0 = make_float2(0, 0), a1 = make_float2(0, 0);
    int j = s;
    for (; j + 1 < e; j += 2) {
        int s0 = csrsrc[j], s1 = csrsrc[j + 1];
        float2 v0 = *(const float2*)(P + (size_t)s0 * 64 + lane * 2);
        float2 v1 = *(const float2*)(P + (size_t)s1 * 64 + lane * 2);
        a0.x += v0.x; a0.y += v0.y;
        a1.x += v1.x; a1.y += v1.y;
    }
    if (j < e) {
        int s0 = csrsrc[j];
        float2 v0 = *(const float2*)(P + (size_t)s0 * 64 + lane * 2);
        a0.x += v0.x; a0.y += v0.y;
    }
    float iv = invdeg[gw];
    float2 cur = *(float2*)(out + (size_t)gw * 64 + lane * 2);
    cur.x += (a0.x + a1.x) * iv;
    cur.y += (a0.y + a1.y) * iv;
    *(float2*)(out + (size_t)gw * 64 + lane * 2) = cur;
}

// ===================== tf32 mma dense, warp-per-16-rows, fused epilogue ==========
// MODE 1: out = [Agg|Hin]@[Wl|Wr]^T + bl, then LN+ReLU  (DO=128)
// MODE 2: single phase K=DI: cols 0..63 -> out2 = Hin@Wl^T (no bias),
//         cols 64..127 -> out = Hin@Wr^T + bl            (DO=128)
template <int DI, int DO, int MODE>
__global__ __launch_bounds__(256) void k_mma(TowerArgs ta, TowerArgs tb) {
    constexpr int NI = DO / 8;                 // 16
    constexpr int PH = (MODE == 2) ? 1 : 2;

    const TowerArgs T = (blockIdx.y == 0) ? ta : tb;

    __shared__ float As[128 * ST];
    __shared__ float Ws[DO * ST];
    __shared__ float prm[3 * DO];

    const int tid  = threadIdx.x;
    const int wid  = tid >> 5;
    const int lane = tid & 31;
    const int g    = lane >> 2;
    const int tig  = lane & 3;
    const int bm   = blockIdx.x * 128;

    if (tid < DO) {
        if (MODE == 2) {
            prm[tid] = (tid < 64) ? 0.f : T.bl[tid - 64];
        } else {
            prm[tid] = T.bl[tid];
            prm[DO + tid] = T.gam[tid];
            prm[2 * DO + tid] = T.bet[tid];
        }
    }

    float acc[NI][4];
    #pragma unroll
    for (int ni = 0; ni < NI; ++ni)
        #pragma unroll
        for (int q = 0; q < 4; ++q) acc[ni][q] = 0.f;

    #pragma unroll
    for (int ph = 0; ph < PH; ++ph) {
        const float* __restrict__ Asrc = (MODE == 2) ? T.Hin : (ph ? T.Hin : T.Agg);
        #pragma unroll
        for (int c = 0; c < DI / 32; ++c) {
            const int kl = c * 32;
            // A tile: 128 rows x 32 floats
            #pragma unroll
            for (int i = 0; i < 4; ++i) {
                int flat = tid + i * 256;
                int row = flat >> 3, q = flat & 7;
                int m = bm + row;
                float4 v = make_float4(0.f, 0.f, 0.f, 0.f);
                if (m < NN) v = *(const float4*)(Asrc + (size_t)m * DI + kl + q * 4);
                v.x = to_tf32(v.x); v.y = to_tf32(v.y); v.z = to_tf32(v.z); v.w = to_tf32(v.w);
                *(float4*)(As + row * ST + q * 4) = v;
            }
            // W tile: DO rows x 32 floats
            #pragma unroll
            for (int i = 0; i < DO / 32; ++i) {
                int flat = tid + i * 256;
                int row = flat >> 3, q = flat & 7;
                const float* __restrict__ Wsrc;
                int wrow = row;
                if (MODE == 2) {
                    if (row < 64) { Wsrc = T.Wl; }
                    else          { Wsrc = T.Wr; wrow = row - 64; }
                } else {
                    Wsrc = ph ? T.Wr : T.Wl;
                }
                float4 v = *(const float4*)(Wsrc + (size_t)wrow * DI + kl + q * 4);
                v.x = to_tf32(v.x); v.y = to_tf32(v.y); v.z = to_tf32(v.z); v.w = to_tf32(v.w);
                *(float4*)(Ws + row * ST + q * 4) = v;
            }
            __syncthreads();

            const int rb = wid * 16;
            #pragma unroll
            for (int kk = 0; kk < 4; ++kk) {
                const int kb = kk * 8;
                uint32_t a0 = __float_as_uint(As[(rb + g) * ST + kb + tig]);
                uint32_t a1 = __float_as_uint(As[(rb + g + 8) * ST + kb + tig]);
                uint32_t a2 = __float_as_uint(As[(rb + g) * ST + kb + tig + 4]);
                uint32_t a3 = __float_as_uint(As[(rb + g + 8) * ST + kb + tig + 4]);
                #pragma unroll
                for (int ni = 0; ni < NI; ++ni) {
                    int nb = ni * 8;
                    uint32_t b0 = __float_as_uint(Ws[(nb + g) * ST + kb + tig]);
                    uint32_t b1 = __float_as_uint(Ws[(nb + g) * ST + kb + tig + 4]);
                    mma_tf32(acc[ni][0], acc[ni][1], acc[ni][2], acc[ni][3],
                             a0, a1, a2, a3, b0, b1);
                }
            }
            __syncthreads();
        }
    }

    // ---- epilogue: bias (+LN+ReLU) ----
    const int r0 = bm + wid * 16 + g;
    const int r1 = r0 + 8;

    #pragma unroll
    for (int ni = 0; ni < NI; ++ni) {
        int col = ni * 8 + tig * 2;
        float b0 = prm[col], b1 = prm[col + 1];
        acc[ni][0] += b0; acc[ni][1] += b1;
        acc[ni][2] += b0; acc[ni][3] += b1;
    }

    if (MODE == 1) {
        float s0 = 0.f, s1 = 0.f;
        #pragma unroll
        for (int ni = 0; ni < NI; ++ni) {
            s0 += acc[ni][0] + acc[ni][1];
            s1 += acc[ni][2] + acc[ni][3];
        }
        s0 += __shfl_xor_sync(0xFFFFFFFF, s0, 1);
        s0 += __shfl_xor_sync(0xFFFFFFFF, s0, 2);
        s1 += __shfl_xor_sync(0xFFFFFFFF, s1, 1);
        s1 += __shfl_xor_sync(0xFFFFFFFF, s1, 2);
        float m0 = s0 * (1.0f / DO), m1 = s1 * (1.0f / DO);
        float q0 = 0.f, q1 = 0.f;
        #pragma unroll
        for (int ni = 0; ni < NI; ++ni) {
            float d0 = acc[ni][0] - m0, d1 = acc[ni][1] - m0;
            float d2 = acc[ni][2] - m1, d3 = acc[ni][3] - m1;
            q0 += d0 * d0 + d1 * d1;
            q1 += d2 * d2 + d3 * d3;
        }
        q0 += __shfl_xor_sync(0xFFFFFFFF, q0, 1);
        q0 += __shfl_xor_sync(0xFFFFFFFF, q0, 2);
        q1 += __shfl_xor_sync(0xFFFFFFFF, q1, 1);
        q1 += __shfl_xor_sync(0xFFFFFFFF, q1, 2);
        float rs0 = rsqrtf(q0 * (1.0f / DO) + LN_EPS);
        float rs1 = rsqrtf(q1 * (1.0f / DO) + LN_EPS);
        #pragma unroll
        for (int ni = 0; ni < NI; ++ni) {
            int col = ni * 8 + tig * 2;
            float g0 = prm[DO + col], g1 = prm[DO + col + 1];
            float bb0 = prm[2 * DO + col], bb1 = prm[2 * DO + col + 1];
            acc[ni][0] = fmaxf((acc[ni][0] - m0) * rs0 * g0 + bb0, 0.f);
            acc[ni][1] = fmaxf((acc[ni][1] - m0) * rs0 * g1 + bb1, 0.f);
            acc[ni][2] = fmaxf((acc[ni][2] - m1) * rs1 * g0 + bb0, 0.f);
            acc[ni][3] = fmaxf((acc[ni][3] - m1) * rs1 * g1 + bb1, 0.f);
        }
    }

    if (MODE == 2) {
        #pragma unroll
        for (int ni = 0; ni < NI; ++ni) {
            if (ni < 8) {  // P = Hin @ Wl^T -> out2
                int col = ni * 8 + tig * 2;
                if (r0 < NN)
                    *(float2*)(T.out2 + (size_t)r0 * 64 + col) =
                        make_float2(acc[ni][0], acc[ni][1]);
                if (r1 < NN)
                    *(float2*)(T.out2 + (size_t)r1 * 64 + col) =
                        make_float2(acc[ni][2], acc[ni][3]);
            } else {       // R = Hin @ Wr^T + bl -> out
                int col = (ni - 8) * 8 + tig * 2;
                if (r0 < NN)
                    *(float2*)(T.out + (size_t)r0 * 64 + col) =
                        make_float2(acc[ni][0], acc[ni][1]);
                if (r1 < NN)
                    *(float2*)(T.out + (size_t)r1 * 64 + col) =
                        make_float2(acc[ni][2], acc[ni][3]);
            }
        }
    } else {
        #pragma unroll
        for (int ni = 0; ni < NI; ++ni) {
            int col = ni * 8 + tig * 2;
            if (r0 < NN)
                *(float2*)(T.out + (size_t)r0 * DO + col) =
                    make_float2(acc[ni][0], acc[ni][1]);
            if (r1 < NN)
                *(float2*)(T.out + (size_t)r1 * DO + col) =
                    make_float2(acc[ni][2], acc[ni][3]);
        }
    }
}

// ===================== host =====================
extern "C" void kernel_launch(void* const* d_in, const int* in_sizes, int n_in,
                              void* d_out, int out_size) {
    const float* x   = (const float*)d_in[0];
    const int*   ei  = (const int*)d_in[1];
    const int*   src = ei;
    const int*   dst = ei + EE;

    int *pDeg, *pRow, *pCur, *pCsr;
    float *pInv, *pAgg0, *pH0, *pAgg1, *pH1, *pP;
    cudaGetSymbolAddress((void**)&pDeg, g_deg);
    cudaGetSymbolAddress((void**)&pRow, g_rowptr);
    cudaGetSymbolAddress((void**)&pCur, g_cursor);
    cudaGetSymbolAddress((void**)&pCsr, g_csrsrc);
    cudaGetSymbolAddress((void**)&pInv, g_invdeg);
    cudaGetSymbolAddress((void**)&pAgg0, g_agg0);
    cudaGetSymbolAddress((void**)&pH0, g_h0);
    cudaGetSymbolAddress((void**)&pAgg1, g_agg1);
    cudaGetSymbolAddress((void**)&pH1, g_h1);
    cudaGetSymbolAddress((void**)&pP, g_P);

    float* h0[2]   = {pH0, pH0 + (size_t)NN * 128};
    float* agg1[2] = {pAgg1, pAgg1 + (size_t)NN * 128};
    float* h1[2]   = {pH1, pH1 + (size_t)NN * 128};
    float* P[2]    = {pP, pP + (size_t)NN * 64};
    float* outT[2] = {(float*)d_out, (float*)d_out + (size_t)NN * 64};

    const float* W[2][13];
    for (int t = 0; t < 2; ++t)
        for (int i = 0; i < 13; ++i) W[t][i] = (const float*)d_in[2 + t * 13 + i];
    // index map: 0 Wl0, 1 bl0, 2 Wr0, 3 g0, 4 b0, 5 Wl1, 6 bl1, 7 Wr1, 8 g1, 9 b1,
    //            10 Wl2, 11 bl2, 12 Wr2

    const int EB = (EE + 255) / 256;
    const int NB = (NN + 255) / 256;
    const int GW = (NN * 32 + 255) / 256;
    const int DB = (NN + 127) / 128;

    cudaMemsetAsync(pDeg, 0, NN * sizeof(int), 0);
    k_count<<<EB, 256>>>(dst, pDeg);
    k_scan<<<1, 1024>>>(pDeg, pRow, pCur);
    k_invdeg<<<NB, 256>>>(pDeg, pInv);
    k_scatter<<<EB, 256>>>(src, dst, pCur, pCsr);

    // shared input aggregation
    k_gather64<<<GW, 256>>>(x, pAgg0, pRow, pCsr, pInv);

    TowerArgs a0, b0;
    // ---- layer 0: [agg0 | x] -> h0 (+LN+ReLU) ----
    a0 = {pAgg0, x, W[0][0], W[0][2], W[0][1], W[0][3], W[0][4], h0[0], nullptr};
    b0 = {pAgg0, x, W[1][0], W[1][2], W[1][1], W[1][3], W[1][4], h0[1], nullptr};
    k_mma<64, 128, 1><<<dim3(DB, 2), 256>>>(a0, b0);

    // ---- layer 1 ----
    k_gather128_2<<<dim3(GW, 2), 256>>>(h0[0], agg1[0], h0[1], agg1[1], pRow, pCsr, pInv);
    a0 = {agg1[0], h0[0], W[0][5], W[0][7], W[0][6], W[0][8], W[0][9], h1[0], nullptr};
    b0 = {agg1[1], h0[1], W[1][5], W[1][7], W[1][6], W[1][8], W[1][9], h1[1], nullptr};
    k_mma<128, 128, 1><<<dim3(DB, 2), 256>>>(a0, b0);

    // ---- layer 2 (commuted aggregation) ----
    a0 = {nullptr, h1[0], W[0][10], W[0][12], W[0][11], nullptr, nullptr, outT[0], P[0]};
    b0 = {nullptr, h1[1], W[1][10], W[1][12], W[1][11], nullptr, nullptr, outT[1], P[1]};
    k_mma<128, 128, 2><<<dim3(DB, 2), 256>>>(a0, b0);
    k_gadd64_2<<<dim3(GW, 2), 256>>>(P[0], outT[0], P[1], outT[1], pRow, pCsr, pInv);
}

// round 5
// speedup vs baseline: 1.0813x; 1.0813x over previous
#include <cuda_runtime.h>
#include <cuda_bf16.h>
#include <cstdint>

#define NN 50000
#define EE 800000
#define LN_EPS 1e-5f
#define ST 36

// ===================== static scratch =====================
__device__ int   g_deg[NN];
__device__ int   g_rowptr[NN + 1];
__device__ int   g_cursor[NN];
__device__ int   g_csrsrc[EE];
__device__ float g_invdeg[NN];
__device__ float g_agg0[(size_t)NN * 64];
__device__ float g_h0[2][(size_t)NN * 128];
__device__ float g_agg1[2][(size_t)NN * 128];
__device__ float g_h1[2][(size_t)NN * 128];
__device__ float g_P[2][(size_t)NN * 64];

struct TowerArgs {
    const float *Agg, *Hin, *Wl, *Wr, *bl, *gam, *bet;
    float *out, *out2;
};

__device__ __forceinline__ float to_tf32(float x) {
    uint32_t u;
    asm("cvt.rna.tf32.f32 %0, %1;" : "=r"(u) : "f"(x));
    return __uint_as_float(u);
}

__device__ __forceinline__ void mma_tf32(float& d0, float& d1, float& d2, float& d3,
                                         uint32_t a0, uint32_t a1, uint32_t a2, uint32_t a3,
                                         uint32_t b0, uint32_t b1) {
    asm volatile(
        "mma.sync.aligned.m16n8k8.row.col.f32.tf32.tf32.f32 "
        "{%0,%1,%2,%3}, {%4,%5,%6,%7}, {%8,%9}, {%0,%1,%2,%3};"
        : "+f"(d0), "+f"(d1), "+f"(d2), "+f"(d3)
        : "r"(a0), "r"(a1), "r"(a2), "r"(a3), "r"(b0), "r"(b1));
}

// ===================== CSR build =====================
__global__ void k_count(const int* __restrict__ dst, int* __restrict__ deg) {
    int e = blockIdx.x * blockDim.x + threadIdx.x;
    if (e < EE) atomicAdd(&deg[dst[e]], 1);
}

__global__ void k_scan(const int* __restrict__ deg, int* __restrict__ rowptr,
                       int* __restrict__ cursor) {
    __shared__ int sums[1024];
    const int t = threadIdx.x;
    const int CH = (NN + 1023) / 1024;
    int s = 0;
    #pragma unroll 4
    for (int i = 0; i < CH; ++i) {
        int idx = t * CH + i;
        if (idx < NN) s += deg[idx];
    }
    sums[t] = s;
    __syncthreads();
    for (int off = 1; off < 1024; off <<= 1) {
        int v = 0;
        if (t >= off) v = sums[t - off];
        __syncthreads();
        if (t >= off) sums[t] += v;
        __syncthreads();
    }
    int run = (t == 0) ? 0 : sums[t - 1];
    for (int i = 0; i < CH; ++i) {
        int idx = t * CH + i;
        if (idx < NN) {
            rowptr[idx] = run;
            cursor[idx] = run;
            run += deg[idx];
        }
    }
    if (t == 1023) rowptr[NN] = run;
}

__global__ void k_invdeg(const int* __restrict__ deg, float* __restrict__ invdeg) {
    int n = blockIdx.x * blockDim.x + threadIdx.x;
    if (n < NN) {
        int d = deg[n];
        invdeg[n] = 1.0f / (float)(d > 0 ? d : 1);
    }
}

__global__ void k_scatter(const int* __restrict__ src, const int* __restrict__ dst,
                          int* __restrict__ cursor, int* __restrict__ csrsrc) {
    int e = blockIdx.x * blockDim.x + threadIdx.x;
    if (e < EE) {
        int pos = atomicAdd(&cursor[dst[e]], 1);
        csrsrc[pos] = src[e];
    }
}

// ===================== gathers =====================
__global__ void k_gather64(const float* __restrict__ h, float* __restrict__ out,
                           const int* __restrict__ rowptr, const int* __restrict__ csrsrc,
                           const float* __restrict__ invdeg) {
    int gw   = (blockIdx.x * blockDim.x + threadIdx.x) >> 5;
    int lane = threadIdx.x & 31;
    if (gw >= NN) return;
    int s = rowptr[gw], e = rowptr[gw + 1];
    float2 a0 = make_float2(0, 0), a1 = make_float2(0, 0);
    int j = s;
    for (; j + 1 < e; j += 2) {
        int s0 = csrsrc[j], s1 = csrsrc[j + 1];
        float2 v0 = *(const float2*)(h + (size_t)s0 * 64 + lane * 2);
        float2 v1 = *(const float2*)(h + (size_t)s1 * 64 + lane * 2);
        a0.x += v0.x; a0.y += v0.y;
        a1.x += v1.x; a1.y += v1.y;
    }
    if (j < e) {
        int s0 = csrsrc[j];
        float2 v0 = *(const float2*)(h + (size_t)s0 * 64 + lane * 2);
        a0.x += v0.x; a0.y += v0.y;
    }
    float iv = invdeg[gw];
    float2 r;
    r.x = (a0.x + a1.x) * iv; r.y = (a0.y + a1.y) * iv;
    *(float2*)(out + (size_t)gw * 64 + lane * 2) = r;
}

__global__ void k_gather128_2(const float* __restrict__ hA, float* __restrict__ oA,
                              const float* __restrict__ hB, float* __restrict__ oB,
                              const int* __restrict__ rowptr, const int* __restrict__ csrsrc,
                              const float* __restrict__ invdeg) {
    const float* __restrict__ h = blockIdx.y ? hB : hA;
    float* __restrict__ out     = blockIdx.y ? oB : oA;
    int gw   = (blockIdx.x * blockDim.x + threadIdx.x) >> 5;
    int lane = threadIdx.x & 31;
    if (gw >= NN) return;
    int s = rowptr[gw], e = rowptr[gw + 1];
    float4 a0 = make_float4(0, 0, 0, 0), a1 = make_float4(0, 0, 0, 0);
    int j = s;
    for (; j + 1 < e; j += 2) {
        int s0 = csrsrc[j], s1 = csrsrc[j + 1];
        float4 v0 = *(const float4*)(h + (size_t)s0 * 128 + lane * 4);
        float4 v1 = *(const float4*)(h + (size_t)s1 * 128 + lane * 4);
        a0.x += v0.x; a0.y += v0.y; a0.z += v0.z; a0.w += v0.w;
        a1.x += v1.x; a1.y += v1.y; a1.z += v1.z; a1.w += v1.w;
    }
    if (j < e) {
        int s0 = csrsrc[j];
        float4 v0 = *(const float4*)(h + (size_t)s0 * 128 + lane * 4);
        a0.x += v0.x; a0.y += v0.y; a0.z += v0.z; a0.w += v0.w;
    }
    float iv = invdeg[gw];
    float4 r;
    r.x = (a0.x + a1.x) * iv; r.y = (a0.y + a1.y) * iv;
    r.z = (a0.z + a1.z) * iv; r.w = (a0.w + a1.w) * iv;
    *(float4*)(out + (size_t)gw * 128 + lane * 4) = r;
}

// mean-gather of 64-wide P, ADD into out (layer-2 commuted aggregation), dual tower
__global__ void k_gadd64_2(const float* __restrict__ PA, float* __restrict__ oA,
                           const float* __restrict__ PB, float* __restrict__ oB,
                           const int* __restrict__ rowptr, const int* __restrict__ csrsrc,
                           const float* __restrict__ invdeg) {
    const float* __restrict__ P = blockIdx.y ? PB : PA;
    float* __restrict__ out     = blockIdx.y ? oB : oA;
    int gw   = (blockIdx.x * blockDim.x + threadIdx.x) >> 5;
    int lane = threadIdx.x & 31;
    if (gw >= NN) return;
    int s = rowptr[gw], e = rowptr[gw + 1];
    float2 a0 = make_float2(0, 0), a1 = make_float2(0, 0);
    int j = s;
    for (; j + 1 < e; j += 2) {
        int s0 = csrsrc[j], s1 = csrsrc[j + 1];
        float2 v0 = *(const float2*)(P + (size_t)s0 * 64 + lane * 2);
        float2 v1 = *(const float2*)(P + (size_t)s1 * 64 + lane * 2);
        a0.x += v0.x; a0.y += v0.y;
        a1.x += v1.x; a1.y += v1.y;
    }
    if (j < e) {
        int s0 = csrsrc[j];
        float2 v0 = *(const float2*)(P + (size_t)s0 * 64 + lane * 2);
        a0.x += v0.x; a0.y += v0.y;
    }
    float iv = invdeg[gw];
    float2 cur = *(float2*)(out + (size_t)gw * 64 + lane * 2);
    cur.x += (a0.x + a1.x) * iv;
    cur.y += (a0.y + a1.y) * iv;
    *(float2*)(out + (size_t)gw * 64 + lane * 2) = cur;
}

// ===================== tf32 mma dense (round-3 tiling) =====================
// 8 warps, 4x2 grid; warp tile 32 rows x 64 cols. acc[2][8][4].
// MODE 1: out = [Agg|Hin]@[Wl|Wr]^T + bl, LN+ReLU fused (cross-warp smem reduce)
// MODE 2: K=DI single phase; warp_n=0 -> out2 = Hin@Wl^T ; warp_n=1 -> out = Hin@Wr^T + bl
template <int DI, int DO, int MODE>
__global__ __launch_bounds__(256) void k_mma(TowerArgs ta, TowerArgs tb) {
    constexpr int WN = DO / 2;   // 64
    constexpr int NI = WN / 8;   // 8
    constexpr int PH = (MODE == 2) ? 1 : 2;

    const TowerArgs T = (blockIdx.y == 0) ? ta : tb;

    __shared__ float As[128 * ST];
    __shared__ float Ws[DO * ST];
    __shared__ float prm[3 * DO];
    __shared__ float red[128][4];   // [row][warp_n*2 + {sum, sumsq}]

    const int tid    = threadIdx.x;
    const int wid    = tid >> 5;
    const int lane   = tid & 31;
    const int g      = lane >> 2;
    const int tig    = lane & 3;
    const int warp_m = wid >> 1;
    const int warp_n = wid & 1;
    const int bm     = blockIdx.x * 128;

    if (tid < DO) {
        if (MODE == 2) {
            prm[tid] = (tid < 64) ? 0.f : T.bl[tid - 64];
        } else {
            prm[tid] = T.bl[tid];
            prm[DO + tid] = T.gam[tid];
            prm[2 * DO + tid] = T.bet[tid];
        }
    }

    float acc[2][NI][4];
    #pragma unroll
    for (int mi = 0; mi < 2; ++mi)
        #pragma unroll
        for (int ni = 0; ni < NI; ++ni)
            #pragma unroll
            for (int q = 0; q < 4; ++q) acc[mi][ni][q] = 0.f;

    #pragma unroll
    for (int ph = 0; ph < PH; ++ph) {
        const float* __restrict__ Asrc = (MODE == 2) ? T.Hin : (ph ? T.Hin : T.Agg);
        #pragma unroll
        for (int c = 0; c < DI / 32; ++c) {
            const int kl = c * 32;
            // A tile: 128 rows x 32 floats
            #pragma unroll
            for (int i = 0; i < 4; ++i) {
                int flat = tid + i * 256;
                int row = flat >> 3, q = flat & 7;
                int m = bm + row;
                float4 v = make_float4(0.f, 0.f, 0.f, 0.f);
                if (m < NN) v = *(const float4*)(Asrc + (size_t)m * DI + kl + q * 4);
                v.x = to_tf32(v.x); v.y = to_tf32(v.y); v.z = to_tf32(v.z); v.w = to_tf32(v.w);
                *(float4*)(As + row * ST + q * 4) = v;
            }
            // W tile: DO rows x 32 floats
            #pragma unroll
            for (int i = 0; i < DO / 32; ++i) {
                int flat = tid + i * 256;
                int row = flat >> 3, q = flat & 7;
                const float* __restrict__ Wsrc;
                int wrow = row;
                if (MODE == 2) {
                    if (row < 64) { Wsrc = T.Wl; }
                    else          { Wsrc = T.Wr; wrow = row - 64; }
                } else {
                    Wsrc = ph ? T.Wr : T.Wl;
                }
                float4 v = *(const float4*)(Wsrc + (size_t)wrow * DI + kl + q * 4);
                v.x = to_tf32(v.x); v.y = to_tf32(v.y); v.z = to_tf32(v.z); v.w = to_tf32(v.w);
                *(float4*)(Ws + row * ST + q * 4) = v;
            }
            __syncthreads();

            #pragma unroll
            for (int kk = 0; kk < 4; ++kk) {
                const int kb = kk * 8;
                uint32_t a[2][4];
                #pragma unroll
                for (int mi = 0; mi < 2; ++mi) {
                    int rb = warp_m * 32 + mi * 16;
                    a[mi][0] = __float_as_uint(As[(rb + g) * ST + kb + tig]);
                    a[mi][1] = __float_as_uint(As[(rb + g + 8) * ST + kb + tig]);
                    a[mi][2] = __float_as_uint(As[(rb + g) * ST + kb + tig + 4]);
                    a[mi][3] = __float_as_uint(As[(rb + g + 8) * ST + kb + tig + 4]);
                }
                #pragma unroll
                for (int ni = 0; ni < NI; ++ni) {
                    int nb = warp_n * WN + ni * 8;
                    uint32_t b0 = __float_as_uint(Ws[(nb + g) * ST + kb + tig]);
                    uint32_t b1 = __float_as_uint(Ws[(nb + g) * ST + kb + tig + 4]);
                    #pragma unroll
                    for (int mi = 0; mi < 2; ++mi)
                        mma_tf32(acc[mi][ni][0], acc[mi][ni][1], acc[mi][ni][2], acc[mi][ni][3],
                                 a[mi][0], a[mi][1], a[mi][2], a[mi][3], b0, b1);
                }
            }
            __syncthreads();
        }
    }

    // ---- epilogue ----
    // + bias
    #pragma unroll
    for (int mi = 0; mi < 2; ++mi)
        #pragma unroll
        for (int ni = 0; ni < NI; ++ni) {
            int col = warp_n * WN + ni * 8 + tig * 2;
            acc[mi][ni][0] += prm[col];     acc[mi][ni][1] += prm[col + 1];
            acc[mi][ni][2] += prm[col];     acc[mi][ni][3] += prm[col + 1];
        }

    if (MODE == 1) {
        // per-thread (sum, sumsq) over its 16 cols, for rows r0 (g) and r1 (g+8), both mi
        #pragma unroll
        for (int mi = 0; mi < 2; ++mi) {
            float s0 = 0.f, q0 = 0.f, s1 = 0.f, q1 = 0.f;
            #pragma unroll
            for (int ni = 0; ni < NI; ++ni) {
                s0 += acc[mi][ni][0] + acc[mi][ni][1];
                q0 += acc[mi][ni][0] * acc[mi][ni][0] + acc[mi][ni][1] * acc[mi][ni][1];
                s1 += acc[mi][ni][2] + acc[mi][ni][3];
                q1 += acc[mi][ni][2] * acc[mi][ni][2] + acc[mi][ni][3] * acc[mi][ni][3];
            }
            s0 += __shfl_xor_sync(0xFFFFFFFF, s0, 1); s0 += __shfl_xor_sync(0xFFFFFFFF, s0, 2);
            q0 += __shfl_xor_sync(0xFFFFFFFF, q0, 1); q0 += __shfl_xor_sync(0xFFFFFFFF, q0, 2);
            s1 += __shfl_xor_sync(0xFFFFFFFF, s1, 1); s1 += __shfl_xor_sync(0xFFFFFFFF, s1, 2);
            q1 += __shfl_xor_sync(0xFFFFFFFF, q1, 1); q1 += __shfl_xor_sync(0xFFFFFFFF, q1, 2);
            if (tig == 0) {
                int row0 = warp_m * 32 + mi * 16 + g;
                red[row0][warp_n * 2 + 0] = s0;
                red[row0][warp_n * 2 + 1] = q0;
                red[row0 + 8][warp_n * 2 + 0] = s1;
                red[row0 + 8][warp_n * 2 + 1] = q1;
            }
        }
        __syncthreads();
        #pragma unroll
        for (int mi = 0; mi < 2; ++mi) {
            int row0 = warp_m * 32 + mi * 16 + g;
            float sA = red[row0][0] + red[row0][2];
            float qA = red[row0][1] + red[row0][3];
            float sB = red[row0 + 8][0] + red[row0 + 8][2];
            float qB = red[row0 + 8][1] + red[row0 + 8][3];
            float m0 = sA * (1.0f / DO);
            float v0 = qA * (1.0f / DO) - m0 * m0;
            float rs0 = rsqrtf(v0 + LN_EPS);
            float m1 = sB * (1.0f / DO);
            float v1 = qB * (1.0f / DO) - m1 * m1;
            float rs1 = rsqrtf(v1 + LN_EPS);
            #pragma unroll
            for (int ni = 0; ni < NI; ++ni) {
                int col = warp_n * WN + ni * 8 + tig * 2;
                float g0 = prm[DO + col], g1 = prm[DO + col + 1];
                float bb0 = prm[2 * DO + col], bb1 = prm[2 * DO + col + 1];
                acc[mi][ni][0] = fmaxf((acc[mi][ni][0] - m0) * rs0 * g0 + bb0, 0.f);
                acc[mi][ni][1] = fmaxf((acc[mi][ni][1] - m0) * rs0 * g1 + bb1, 0.f);
                acc[mi][ni][2] = fmaxf((acc[mi][ni][2] - m1) * rs1 * g0 + bb0, 0.f);
                acc[mi][ni][3] = fmaxf((acc[mi][ni][3] - m1) * rs1 * g1 + bb1, 0.f);
            }
        }
    }

    // ---- stores ----
    if (MODE == 2) {
        float* dstp = warp_n ? T.out : T.out2;
        #pragma unroll
        for (int ni = 0; ni < NI; ++ni) {
            int col = ni * 8 + tig * 2;   // 0..63 within the 64-wide dest
            #pragma unroll
            for (int mi = 0; mi < 2; ++mi) {
                int r0 = bm + warp_m * 32 + mi * 16 + g;
                if (r0 < NN)
                    *(float2*)(dstp + (size_t)r0 * 64 + col) =
                        make_float2(acc[mi][ni][0], acc[mi][ni][1]);
                int r1 = r0 + 8;
                if (r1 < NN)
                    *(float2*)(dstp + (size_t)r1 * 64 + col) =
                        make_float2(acc[mi][ni][2], acc[mi][ni][3]);
            }
        }
    } else {
        #pragma unroll
        for (int ni = 0; ni < NI; ++ni) {
            int col = warp_n * WN + ni * 8 + tig * 2;
            #pragma unroll
            for (int mi = 0; mi < 2; ++mi) {
                int r0 = bm + warp_m * 32 + mi * 16 + g;
                if (r0 < NN)
                    *(float2*)(T.out + (size_t)r0 * DO + col) =
                        make_float2(acc[mi][ni][0], acc[mi][ni][1]);
                int r1 = r0 + 8;
                if (r1 < NN)
                    *(float2*)(T.out + (size_t)r1 * DO + col) =
                        make_float2(acc[mi][ni][2], acc[mi][ni][3]);
            }
        }
    }
}

// ===================== host =====================
extern "C" void kernel_launch(void* const* d_in, const int* in_sizes, int n_in,
                              void* d_out, int out_size) {
    const float* x   = (const float*)d_in[0];
    const int*   ei  = (const int*)d_in[1];
    const int*   src = ei;
    const int*   dst = ei + EE;

    int *pDeg, *pRow, *pCur, *pCsr;
    float *pInv, *pAgg0, *pH0, *pAgg1, *pH1, *pP;
    cudaGetSymbolAddress((void**)&pDeg, g_deg);
    cudaGetSymbolAddress((void**)&pRow, g_rowptr);
    cudaGetSymbolAddress((void**)&pCur, g_cursor);
    cudaGetSymbolAddress((void**)&pCsr, g_csrsrc);
    cudaGetSymbolAddress((void**)&pInv, g_invdeg);
    cudaGetSymbolAddress((void**)&pAgg0, g_agg0);
    cudaGetSymbolAddress((void**)&pH0, g_h0);
    cudaGetSymbolAddress((void**)&pAgg1, g_agg1);
    cudaGetSymbolAddress((void**)&pH1, g_h1);
    cudaGetSymbolAddress((void**)&pP, g_P);

    float* h0[2]   = {pH0, pH0 + (size_t)NN * 128};
    float* agg1[2] = {pAgg1, pAgg1 + (size_t)NN * 128};
    float* h1[2]   = {pH1, pH1 + (size_t)NN * 128};
    float* P[2]    = {pP, pP + (size_t)NN * 64};
    float* outT[2] = {(float*)d_out, (float*)d_out + (size_t)NN * 64};

    const float* W[2][13];
    for (int t = 0; t < 2; ++t)
        for (int i = 0; i < 13; ++i) W[t][i] = (const float*)d_in[2 + t * 13 + i];

    const int EB = (EE + 255) / 256;
    const int NB = (NN + 255) / 256;
    const int GW = (NN * 32 + 255) / 256;
    const int DB = (NN + 127) / 128;

    cudaMemsetAsync(pDeg, 0, NN * sizeof(int), 0);
    k_count<<<EB, 256>>>(dst, pDeg);
    k_scan<<<1, 1024>>>(pDeg, pRow, pCur);
    k_invdeg<<<NB, 256>>>(pDeg, pInv);
    k_scatter<<<EB, 256>>>(src, dst, pCur, pCsr);

    k_gather64<<<GW, 256>>>(x, pAgg0, pRow, pCsr, pInv);

    TowerArgs a0, b0;
    // ---- layer 0: [agg0 | x] -> h0 (+LN+ReLU fused) ----
    a0 = {pAgg0, x, W[0][0], W[0][2], W[0][1], W[0][3], W[0][4], h0[0], nullptr};
    b0 = {pAgg0, x, W[1][0], W[1][2], W[1][1], W[1][3], W[1][4], h0[1], nullptr};
    k_mma<64, 128, 1><<<dim3(DB, 2), 256>>>(a0, b0);

    // ---- layer 1 ----
    k_gather128_2<<<dim3(GW, 2), 256>>>(h0[0], agg1[0], h0[1], agg1[1], pRow, pCsr, pInv);
    a0 = {agg1[0], h0[0], W[0][5], W[0][7], W[0][6], W[0][8], W[0][9], h1[0], nullptr};
    b0 = {agg1[1], h0[1], W[1][5], W[1][7], W[1][6], W[1][8], W[1][9], h1[1], nullptr};
    k_mma<128, 128, 1><<<dim3(DB, 2), 256>>>(a0, b0);

    // ---- layer 2 (commuted aggregation) ----
    a0 = {nullptr, h1[0], W[0][10], W[0][12], W[0][11], nullptr, nullptr, outT[0], P[0]};
    b0 = {nullptr, h1[1], W[1][10], W[1][12], W[1][11], nullptr, nullptr, outT[1], P[1]};
    k_mma<128, 128, 2><<<dim3(DB, 2), 256>>>(a0, b0);
    k_gadd64_2<<<dim3(GW, 2), 256>>>(P[0], outT[0], P[1], outT[1], pRow, pCsr, pInv);
}